// round 1
// baseline (speedup 1.0000x reference)
#include <cuda_runtime.h>
#include <cuda_bf16.h>
#include <cstdint>

#define NUM_EXPERT 16
#define IN_FEAT 1024
#define OUT_FEAT 1024
#define BATCH 8192

#define BM 128
#define BN 128
#define BK 16

// Scratch (no allocations allowed): expert bins.
__device__ int g_counts[NUM_EXPERT];
__device__ int g_rows[NUM_EXPERT * BATCH];

__global__ void reset_counts_kernel() {
    if (threadIdx.x < NUM_EXPERT) g_counts[threadIdx.x] = 0;
}

__global__ void scatter_kernel(const int* __restrict__ gate) {
    int t = blockIdx.x * blockDim.x + threadIdx.x;
    if (t < BATCH) {
        int e = gate[t];
        int pos = atomicAdd(&g_counts[e], 1);
        g_rows[e * BATCH + pos] = t;
    }
}

// Grouped GEMM: out[r, n] = sum_k inp[r, k] * weight[e, n, k] for rows r routed
// to expert e. Each block: one (expert, row-tile, col-tile). 256 threads,
// each computes an 8x8 micro-tile of the 128x128 block tile.
__global__ __launch_bounds__(256, 2)
void moe_gemm_kernel(const float* __restrict__ inp,
                     const float* __restrict__ weight,
                     float* __restrict__ out) {
    const int e = blockIdx.z;
    const int cnt = g_counts[e];
    const int row0 = blockIdx.y * BM;
    if (row0 >= cnt) return;
    const int col0 = blockIdx.x * BN;

    __shared__ float As[BK][BM];        // A tile, k-major rows for coalesced compute reads
    __shared__ float Bs[BK][BN + 4];    // +4 pad to soften LDS conflicts
    __shared__ int srows[BM];

    const int tid = threadIdx.x;

    if (tid < BM) {
        int r = row0 + tid;
        srows[tid] = (r < cnt) ? g_rows[e * BATCH + r] : -1;
    }
    __syncthreads();

    const float* wbase = weight + (size_t)e * OUT_FEAT * IN_FEAT;

    float acc[8][8];
    #pragma unroll
    for (int i = 0; i < 8; i++)
        #pragma unroll
        for (int j = 0; j < 8; j++) acc[i][j] = 0.0f;

    const int tm = (tid / 16) * 8;   // 16x16 thread grid over the 128x128 tile
    const int tn = (tid % 16) * 8;

    for (int k0 = 0; k0 < IN_FEAT; k0 += BK) {
        // --- Load A tile (gathered rows): 128 rows x 16 k = 512 float4s, 2/thread
        #pragma unroll
        for (int it = 0; it < 2; it++) {
            int idx = tid * 2 + it;          // 0..511
            int m   = idx >> 2;              // row within tile
            int kk  = (idx & 3) * 4;         // k offset within tile
            int r = srows[m];
            float4 v = make_float4(0.f, 0.f, 0.f, 0.f);
            if (r >= 0)
                v = *reinterpret_cast<const float4*>(inp + (size_t)r * IN_FEAT + k0 + kk);
            As[kk + 0][m] = v.x;
            As[kk + 1][m] = v.y;
            As[kk + 2][m] = v.z;
            As[kk + 3][m] = v.w;
        }
        // --- Load B tile: weight rows col0..col0+127, k slice
        #pragma unroll
        for (int it = 0; it < 2; it++) {
            int idx = tid * 2 + it;
            int n   = idx >> 2;
            int kk  = (idx & 3) * 4;
            float4 v = *reinterpret_cast<const float4*>(
                wbase + (size_t)(col0 + n) * IN_FEAT + k0 + kk);
            Bs[kk + 0][n] = v.x;
            Bs[kk + 1][n] = v.y;
            Bs[kk + 2][n] = v.z;
            Bs[kk + 3][n] = v.w;
        }
        __syncthreads();

        #pragma unroll
        for (int k = 0; k < BK; k++) {
            float a[8], b[8];
            float4 a0 = *reinterpret_cast<const float4*>(&As[k][tm]);
            float4 a1 = *reinterpret_cast<const float4*>(&As[k][tm + 4]);
            float4 b0 = *reinterpret_cast<const float4*>(&Bs[k][tn]);
            float4 b1 = *reinterpret_cast<const float4*>(&Bs[k][tn + 4]);
            a[0]=a0.x; a[1]=a0.y; a[2]=a0.z; a[3]=a0.w;
            a[4]=a1.x; a[5]=a1.y; a[6]=a1.z; a[7]=a1.w;
            b[0]=b0.x; b[1]=b0.y; b[2]=b0.z; b[3]=b0.w;
            b[4]=b1.x; b[5]=b1.y; b[6]=b1.z; b[7]=b1.w;
            #pragma unroll
            for (int i = 0; i < 8; i++)
                #pragma unroll
                for (int j = 0; j < 8; j++)
                    acc[i][j] = fmaf(a[i], b[j], acc[i][j]);
        }
        __syncthreads();
    }

    // --- Epilogue: scatter rows back to out
    #pragma unroll
    for (int i = 0; i < 8; i++) {
        int r = srows[tm + i];
        if (r < 0) continue;
        float* orow = out + (size_t)r * OUT_FEAT + col0 + tn;
        float4 v0 = make_float4(acc[i][0], acc[i][1], acc[i][2], acc[i][3]);
        float4 v1 = make_float4(acc[i][4], acc[i][5], acc[i][6], acc[i][7]);
        *reinterpret_cast<float4*>(orow)     = v0;
        *reinterpret_cast<float4*>(orow + 4) = v1;
    }
}

extern "C" void kernel_launch(void* const* d_in, const int* in_sizes, int n_in,
                              void* d_out, int out_size) {
    const float* inp    = (const float*)d_in[0];   // [8192, 1024] f32
    const int*   gate   = (const int*)d_in[1];     // [8192] i32
    const float* weight = (const float*)d_in[2];   // [16, 1024, 1024] f32
    float* out = (float*)d_out;                    // [8192, 1024] f32

    reset_counts_kernel<<<1, 32>>>();
    scatter_kernel<<<(BATCH + 255) / 256, 256>>>(gate);

    dim3 grid(OUT_FEAT / BN, (BATCH + BM - 1) / BM, NUM_EXPERT);
    moe_gemm_kernel<<<grid, 256>>>(inp, weight, out);
}

// round 5
// speedup vs baseline: 2.5019x; 2.5019x over previous
#include <cuda_runtime.h>
#include <cuda_bf16.h>
#include <cstdint>

#define NUM_EXPERT 16
#define IN_FEAT 1024
#define OUT_FEAT 1024
#define BATCH 8192

#define BM 128
#define BN 128
#define BK 32
#define NCHUNK (IN_FEAT / BK)    // 32
#define THREADS 256
#define SPAD 40                  // bf16 elements per smem row (32 data + 8 pad)
#define TSZ (128 * SPAD * 2)     // one tile stage: 10240 B
#define SMEM_TILES 512           // tiles start after srows
#define SMEM_TOTAL (SMEM_TILES + 8 * TSZ)   // 512 + 81920 = 82432

__device__ int g_counts[NUM_EXPERT];
__device__ int g_rows[NUM_EXPERT * BATCH];

__global__ void reset_counts_kernel() {
    if (threadIdx.x < NUM_EXPERT) g_counts[threadIdx.x] = 0;
}

__global__ void scatter_kernel(const int* __restrict__ gate) {
    int t = blockIdx.x * blockDim.x + threadIdx.x;
    if (t < BATCH) {
        int e = gate[t];
        int pos = atomicAdd(&g_counts[e], 1);
        g_rows[e * BATCH + pos] = t;
    }
}

// ---------------- helpers ----------------
__device__ __forceinline__ uint32_t smem_u32(const void* p) {
    uint32_t a;
    asm("{ .reg .u64 t; cvta.to.shared.u64 t, %1; cvt.u32.u64 %0, t; }" : "=r"(a) : "l"(p));
    return a;
}

// Split (x, y) into packed bf16x2 hi and bf16x2 residual lo.
__device__ __forceinline__ void split2(float x, float y, uint32_t& hi, uint32_t& lo) {
    asm("cvt.rn.bf16x2.f32 %0, %1, %2;" : "=r"(hi) : "f"(y), "f"(x));
    float xh = __uint_as_float(hi << 16);
    float yh = __uint_as_float(hi & 0xFFFF0000u);
    float xl = x - xh;
    float yl = y - yh;
    asm("cvt.rn.bf16x2.f32 %0, %1, %2;" : "=r"(lo) : "f"(yl), "f"(xl));
}

__device__ __forceinline__ void ldsm4(uint32_t* r, uint32_t addr) {
    asm volatile("ldmatrix.sync.aligned.m8n8.x4.shared.b16 {%0,%1,%2,%3}, [%4];"
                 : "=r"(r[0]), "=r"(r[1]), "=r"(r[2]), "=r"(r[3]) : "r"(addr));
}

__device__ __forceinline__ void mma16816(float* d, const uint32_t* a, const uint32_t* b) {
    asm volatile(
        "mma.sync.aligned.m16n8k16.row.col.f32.bf16.bf16.f32 "
        "{%0,%1,%2,%3}, {%4,%5,%6,%7}, {%8,%9}, {%0,%1,%2,%3};"
        : "+f"(d[0]), "+f"(d[1]), "+f"(d[2]), "+f"(d[3])
        : "r"(a[0]), "r"(a[1]), "r"(a[2]), "r"(a[3]), "r"(b[0]), "r"(b[1]));
}

// ---------------- grouped GEMM (bf16 hi/lo split, mma.sync) ----------------
__global__ __launch_bounds__(THREADS, 1)
void moe_mma_kernel(const float* __restrict__ inp,
                    const float* __restrict__ weight,
                    float* __restrict__ out) {
    const int e = blockIdx.z;
    const int cnt = g_counts[e];
    const int row0 = blockIdx.y * BM;
    if (row0 >= cnt) return;
    const int col0 = blockIdx.x * BN;

    extern __shared__ char smem[];
    int* srows = (int*)smem;

    const int tid = threadIdx.x;
    const int wid = tid >> 5;
    const int lane = tid & 31;
    const int warp_m = wid >> 2;      // 0..1 -> 64-row half
    const int warp_n = wid & 3;       // 0..3 -> 32-col quarter

    if (tid < BM) {
        int r = row0 + tid;
        srows[tid] = (r < cnt) ? g_rows[e * BATCH + r] : -1;
    }
    __syncthreads();

    const uint32_t sb  = smem_u32(smem);
    const uint32_t AHI = sb + SMEM_TILES;
    const uint32_t ALO = AHI + 2 * TSZ;
    const uint32_t WHI = ALO + 2 * TSZ;
    const uint32_t WLO = WHI + 2 * TSZ;
    char* cAHI = smem + SMEM_TILES;
    char* cALO = smem + SMEM_TILES + 2 * TSZ;
    char* cWHI = smem + SMEM_TILES + 4 * TSZ;
    char* cWLO = smem + SMEM_TILES + 6 * TSZ;

    // ---- fixed per-thread load assignments (4 float4 of A + 4 of W per chunk)
    const float* wbase = weight + (size_t)e * OUT_FEAT * IN_FEAT + (size_t)col0 * IN_FEAT;
    const float* aptr[4];
    const float* wptr[4];
    uint32_t sts_off[4];
    bool avalid[4];
    #pragma unroll
    for (int i = 0; i < 4; i++) {
        int idx = tid + i * THREADS;   // 0..1023
        int m  = idx >> 3;             // tile row (A) / weight row (W)
        int kf = idx & 7;              // float4 index within BK=32
        sts_off[i] = (uint32_t)(m * SPAD + kf * 4) * 2;
        int r = srows[m];
        avalid[i] = (r >= 0);
        aptr[i] = inp + (size_t)(r < 0 ? 0 : r) * IN_FEAT + kf * 4;
        wptr[i] = wbase + (size_t)m * IN_FEAT + kf * 4;
    }

    // ---- ldmatrix per-lane address offsets (bytes within a tile)
    const int arow  = lane & 15;
    const int akoff = (lane >> 4) << 3;
    const uint32_t a_off = (uint32_t)((warp_m * 64 + arow) * SPAD + akoff) * 2;
    const int brow  = ((lane >> 4) << 3) + (lane & 7);
    const int bkoff = ((lane >> 3) & 1) << 3;
    const uint32_t b_off = (uint32_t)((warp_n * 32 + brow) * SPAD + bkoff) * 2;

    float acc[4][4][4];
    #pragma unroll
    for (int mt = 0; mt < 4; mt++)
        #pragma unroll
        for (int nt = 0; nt < 4; nt++)
            #pragma unroll
            for (int q = 0; q < 4; q++) acc[mt][nt][q] = 0.0f;

    float4 pa[4], pw[4];

    // prologue: fetch chunk 0
    #pragma unroll
    for (int i = 0; i < 4; i++) {
        pa[i] = avalid[i] ? *reinterpret_cast<const float4*>(aptr[i])
                          : make_float4(0.f, 0.f, 0.f, 0.f);
        pw[i] = *reinterpret_cast<const float4*>(wptr[i]);
    }
    #pragma unroll
    for (int i = 0; i < 4; i++) {
        uint32_t h0, l0, h1, l1;
        split2(pa[i].x, pa[i].y, h0, l0);
        split2(pa[i].z, pa[i].w, h1, l1);
        *reinterpret_cast<uint2*>(cAHI + sts_off[i]) = make_uint2(h0, h1);
        *reinterpret_cast<uint2*>(cALO + sts_off[i]) = make_uint2(l0, l1);
        split2(pw[i].x, pw[i].y, h0, l0);
        split2(pw[i].z, pw[i].w, h1, l1);
        *reinterpret_cast<uint2*>(cWHI + sts_off[i]) = make_uint2(h0, h1);
        *reinterpret_cast<uint2*>(cWLO + sts_off[i]) = make_uint2(l0, l1);
    }
    __syncthreads();

    #pragma unroll 1
    for (int c = 0; c < NCHUNK; c++) {
        const int stage = c & 1;
        const uint32_t soff = (uint32_t)stage * TSZ;

        // prefetch next chunk into registers
        if (c + 1 < NCHUNK) {
            const int k0 = (c + 1) * BK;
            #pragma unroll
            for (int i = 0; i < 4; i++) {
                pa[i] = avalid[i] ? *reinterpret_cast<const float4*>(aptr[i] + k0)
                                  : make_float4(0.f, 0.f, 0.f, 0.f);
                pw[i] = *reinterpret_cast<const float4*>(wptr[i] + k0);
            }
        }

        // compute on current stage
        #pragma unroll
        for (int ks = 0; ks < 2; ks++) {
            uint32_t ah[4][4], al[4][4], wh[2][4], wl[2][4];
            #pragma unroll
            for (int mt = 0; mt < 4; mt++) {
                uint32_t t = soff + a_off + ks * 32 + mt * (16 * SPAD * 2);
                ldsm4(ah[mt], AHI + t);
                ldsm4(al[mt], ALO + t);
            }
            #pragma unroll
            for (int ng = 0; ng < 2; ng++) {
                uint32_t t = soff + b_off + ks * 32 + ng * (16 * SPAD * 2);
                ldsm4(wh[ng], WHI + t);
                ldsm4(wl[ng], WLO + t);
            }
            #pragma unroll
            for (int mt = 0; mt < 4; mt++)
                #pragma unroll
                for (int nt = 0; nt < 4; nt++)
                    mma16816(acc[mt][nt], ah[mt], &wh[nt >> 1][(nt & 1) * 2]);
            #pragma unroll
            for (int mt = 0; mt < 4; mt++)
                #pragma unroll
                for (int nt = 0; nt < 4; nt++)
                    mma16816(acc[mt][nt], al[mt], &wh[nt >> 1][(nt & 1) * 2]);
            #pragma unroll
            for (int mt = 0; mt < 4; mt++)
                #pragma unroll
                for (int nt = 0; nt < 4; nt++)
                    mma16816(acc[mt][nt], ah[mt], &wl[nt >> 1][(nt & 1) * 2]);
        }

        // store next chunk into the other stage (safe: last reads of that
        // stage finished before the barrier that ended chunk c-1)
        if (c + 1 < NCHUNK) {
            const uint32_t nsoff = (uint32_t)((c + 1) & 1) * TSZ;
            #pragma unroll
            for (int i = 0; i < 4; i++) {
                uint32_t h0, l0, h1, l1;
                split2(pa[i].x, pa[i].y, h0, l0);
                split2(pa[i].z, pa[i].w, h1, l1);
                *reinterpret_cast<uint2*>(cAHI + nsoff + sts_off[i]) = make_uint2(h0, h1);
                *reinterpret_cast<uint2*>(cALO + nsoff + sts_off[i]) = make_uint2(l0, l1);
                split2(pw[i].x, pw[i].y, h0, l0);
                split2(pw[i].z, pw[i].w, h1, l1);
                *reinterpret_cast<uint2*>(cWHI + nsoff + sts_off[i]) = make_uint2(h0, h1);
                *reinterpret_cast<uint2*>(cWLO + nsoff + sts_off[i]) = make_uint2(l0, l1);
            }
        }
        __syncthreads();
    }

    // ---- epilogue: scatter accumulators to out
    const int rbase = warp_m * 64 + (lane >> 2);
    const int cbase = col0 + warp_n * 32 + (lane & 3) * 2;
    #pragma unroll
    for (int mt = 0; mt < 4; mt++) {
        int r0 = srows[rbase + mt * 16];
        int r1 = srows[rbase + mt * 16 + 8];
        #pragma unroll
        for (int nt = 0; nt < 4; nt++) {
            int col = cbase + nt * 8;
            if (r0 >= 0)
                *reinterpret_cast<float2*>(out + (size_t)r0 * OUT_FEAT + col) =
                    make_float2(acc[mt][nt][0], acc[mt][nt][1]);
            if (r1 >= 0)
                *reinterpret_cast<float2*>(out + (size_t)r1 * OUT_FEAT + col) =
                    make_float2(acc[mt][nt][2], acc[mt][nt][3]);
        }
    }
}

extern "C" void kernel_launch(void* const* d_in, const int* in_sizes, int n_in,
                              void* d_out, int out_size) {
    const float* inp    = (const float*)d_in[0];   // [8192, 1024] f32
    const int*   gate   = (const int*)d_in[1];     // [8192] i32
    const float* weight = (const float*)d_in[2];   // [16, 1024, 1024] f32
    float* out = (float*)d_out;                    // [8192, 1024] f32

    cudaFuncSetAttribute(moe_mma_kernel, cudaFuncAttributeMaxDynamicSharedMemorySize,
                         SMEM_TOTAL);

    reset_counts_kernel<<<1, 32>>>();
    scatter_kernel<<<(BATCH + 255) / 256, 256>>>(gate);

    dim3 grid(OUT_FEAT / BN, BATCH / BM, NUM_EXPERT);
    moe_mma_kernel<<<grid, THREADS, SMEM_TOTAL>>>(inp, weight, out);
}

// round 6
// speedup vs baseline: 3.0920x; 1.2359x over previous
#include <cuda_runtime.h>
#include <cuda_fp16.h>
#include <cstdint>

#define NUM_EXPERT 16
#define IN_FEAT 1024
#define OUT_FEAT 1024
#define BATCH 8192

#define BM 128
#define BN 128
#define BK 32
#define NCHUNK (IN_FEAT / BK)    // 32
#define THREADS 256
#define SPAD 40                  // fp16 elements per smem row (32 data + 8 pad)
#define TSZ (128 * SPAD * 2)     // one tile: 10240 B
#define NSTAGE 3
#define OFF_AHI 0
#define OFF_ALO TSZ
#define OFF_W   (2 * TSZ)
#define STAGE_SZ (3 * TSZ)       // 30720
#define SMEM_TILES 512
#define SMEM_TOTAL (SMEM_TILES + NSTAGE * STAGE_SZ)   // 92672

__device__ int g_counts[NUM_EXPERT];
__device__ int g_rows[NUM_EXPERT * BATCH];
// Precomputed fp16 operands (static scratch; no allocs).
__device__ __align__(16) unsigned short g_whi[NUM_EXPERT * OUT_FEAT * IN_FEAT]; // 33.5 MB
__device__ __align__(16) unsigned short g_ahi[BATCH * IN_FEAT];                 // 16.8 MB
__device__ __align__(16) unsigned short g_alo[BATCH * IN_FEAT];                 // 16.8 MB

// ---------------- helpers ----------------
__device__ __forceinline__ uint32_t smem_u32(const void* p) {
    uint32_t a;
    asm("{ .reg .u64 t; cvta.to.shared.u64 t, %1; cvt.u32.u64 %0, t; }" : "=r"(a) : "l"(p));
    return a;
}
__device__ __forceinline__ uint32_t pack_h2(float x, float y) {
    uint32_t r;
    asm("cvt.rn.f16x2.f32 %0, %1, %2;" : "=r"(r) : "f"(y), "f"(x));  // y->hi, x->lo
    return r;
}
__device__ __forceinline__ void split2h(float x, float y, uint32_t& hi, uint32_t& lo) {
    hi = pack_h2(x, y);
    float xh = __half2float(__ushort_as_half((unsigned short)(hi & 0xFFFF)));
    float yh = __half2float(__ushort_as_half((unsigned short)(hi >> 16)));
    lo = pack_h2(x - xh, y - yh);
}
__device__ __forceinline__ void cp16(uint32_t dst, const void* src, uint32_t bytes) {
    asm volatile("cp.async.cg.shared.global [%0], [%1], 16, %2;"
                 :: "r"(dst), "l"(src), "r"(bytes) : "memory");
}
__device__ __forceinline__ void cp_commit() {
    asm volatile("cp.async.commit_group;" ::: "memory");
}
template <int N>
__device__ __forceinline__ void cp_wait() {
    asm volatile("cp.async.wait_group %0;" :: "n"(N) : "memory");
}
__device__ __forceinline__ void ldsm4(uint32_t* r, uint32_t addr) {
    asm volatile("ldmatrix.sync.aligned.m8n8.x4.shared.b16 {%0,%1,%2,%3}, [%4];"
                 : "=r"(r[0]), "=r"(r[1]), "=r"(r[2]), "=r"(r[3]) : "r"(addr));
}
__device__ __forceinline__ void mma16816(float* d, const uint32_t* a, const uint32_t* b) {
    asm volatile(
        "mma.sync.aligned.m16n8k16.row.col.f32.f16.f16.f32 "
        "{%0,%1,%2,%3}, {%4,%5,%6,%7}, {%8,%9}, {%0,%1,%2,%3};"
        : "+f"(d[0]), "+f"(d[1]), "+f"(d[2]), "+f"(d[3])
        : "r"(a[0]), "r"(a[1]), "r"(a[2]), "r"(a[3]), "r"(b[0]), "r"(b[1]));
}

// ---------------- routing + conversion prepasses ----------------
__global__ void reset_counts_kernel() {
    if (threadIdx.x < NUM_EXPERT) g_counts[threadIdx.x] = 0;
}
__global__ void scatter_kernel(const int* __restrict__ gate) {
    int t = blockIdx.x * blockDim.x + threadIdx.x;
    if (t < BATCH) {
        int e = gate[t];
        int pos = atomicAdd(&g_counts[e], 1);
        g_rows[e * BATCH + pos] = t;
    }
}
__global__ __launch_bounds__(256)
void convert_w_kernel(const float* __restrict__ w) {
    int i = blockIdx.x * blockDim.x + threadIdx.x;   // one float4
    float4 v = reinterpret_cast<const float4*>(w)[i];
    uint2 h;
    h.x = pack_h2(v.x, v.y);
    h.y = pack_h2(v.z, v.w);
    reinterpret_cast<uint2*>(g_whi)[i] = h;
}
__global__ __launch_bounds__(256)
void convert_a_kernel(const float* __restrict__ a) {
    int i = blockIdx.x * blockDim.x + threadIdx.x;   // one float4
    float4 v = reinterpret_cast<const float4*>(a)[i];
    uint2 h, l;
    split2h(v.x, v.y, h.x, l.x);
    split2h(v.z, v.w, h.y, l.y);
    reinterpret_cast<uint2*>(g_ahi)[i] = h;
    reinterpret_cast<uint2*>(g_alo)[i] = l;
}

// ---------------- grouped GEMM (fp16 2-pass, cp.async pipeline) ----------------
__global__ __launch_bounds__(THREADS, 2)
void moe_mma_kernel(float* __restrict__ out) {
    const int e = blockIdx.z;
    const int cnt = g_counts[e];
    const int row0 = blockIdx.y * BM;
    if (row0 >= cnt) return;
    const int col0 = blockIdx.x * BN;

    extern __shared__ char smem[];
    int* srows = (int*)smem;

    const int tid = threadIdx.x;
    const int wid = tid >> 5;
    const int lane = tid & 31;
    const int warp_m = wid >> 2;      // 0..1 -> 64-row half
    const int warp_n = wid & 3;       // 0..3 -> 32-col quarter

    if (tid < BM) {
        int r = row0 + tid;
        srows[tid] = (r < cnt) ? g_rows[e * BATCH + r] : -1;
    }
    __syncthreads();

    const uint32_t sb = smem_u32(smem);
    const uint32_t TILES = sb + SMEM_TILES;

    // ---- per-thread cp.async assignments: 2 x (A_hi, A_lo, W) 16B chunks/chunk
    const unsigned short* ahi_p[2];
    const unsigned short* alo_p[2];
    const unsigned short* w_p[2];
    uint32_t dst_off[2], abytes[2];
    #pragma unroll
    for (int i = 0; i < 2; i++) {
        int idx = tid + i * THREADS;   // 0..511
        int m  = idx >> 2;             // row 0..127
        int kq = idx & 3;              // 16B quarter of the 64B row
        dst_off[i] = (uint32_t)(m * (SPAD * 2) + kq * 16);
        int r = srows[m];
        abytes[i] = (r >= 0) ? 16u : 0u;
        size_t aoff = (size_t)(r < 0 ? 0 : r) * IN_FEAT + kq * 8;
        ahi_p[i] = g_ahi + aoff;
        alo_p[i] = g_alo + aoff;
        w_p[i] = g_whi + ((size_t)e * OUT_FEAT + col0 + m) * IN_FEAT + kq * 8;
    }

    // ---- ldmatrix per-lane offsets (bytes within a tile)
    const int arow  = lane & 15;
    const int akoff = (lane >> 4) << 3;
    const uint32_t a_off = (uint32_t)((warp_m * 64 + arow) * SPAD + akoff) * 2;
    const int brow  = ((lane >> 4) << 3) + (lane & 7);
    const int bkoff = ((lane >> 3) & 1) << 3;
    const uint32_t b_off = (uint32_t)((warp_n * 32 + brow) * SPAD + bkoff) * 2;

    float acc[4][4][4];
    #pragma unroll
    for (int mt = 0; mt < 4; mt++)
        #pragma unroll
        for (int nt = 0; nt < 4; nt++)
            #pragma unroll
            for (int q = 0; q < 4; q++) acc[mt][nt][q] = 0.0f;

    // ---- prologue: prefetch stages 0..2
    #pragma unroll
    for (int s = 0; s < NSTAGE; s++) {
        uint32_t base = TILES + s * STAGE_SZ;
        #pragma unroll
        for (int i = 0; i < 2; i++) {
            cp16(base + OFF_AHI + dst_off[i], ahi_p[i] + s * BK, abytes[i]);
            cp16(base + OFF_ALO + dst_off[i], alo_p[i] + s * BK, abytes[i]);
            cp16(base + OFF_W   + dst_off[i], w_p[i]   + s * BK, 16u);
        }
        cp_commit();
    }

    int stage = 0;
    #pragma unroll 1
    for (int c = 0; c < NCHUNK; c++) {
        cp_wait<NSTAGE - 1>();      // chunk c landed
        __syncthreads();

        const uint32_t soff = TILES + (uint32_t)stage * STAGE_SZ;
        #pragma unroll
        for (int ks = 0; ks < 2; ks++) {
            uint32_t w_[2][4];
            ldsm4(w_[0], soff + OFF_W + b_off + ks * 32);
            ldsm4(w_[1], soff + OFF_W + b_off + ks * 32 + 16 * SPAD * 2);
            #pragma unroll
            for (int mt = 0; mt < 4; mt++) {
                uint32_t a_[4];
                uint32_t at = a_off + ks * 32 + mt * (16 * SPAD * 2);
                ldsm4(a_, soff + OFF_AHI + at);
                #pragma unroll
                for (int nt = 0; nt < 4; nt++)
                    mma16816(acc[mt][nt], a_, &w_[nt >> 1][(nt & 1) * 2]);
                ldsm4(a_, soff + OFF_ALO + at);
                #pragma unroll
                for (int nt = 0; nt < 4; nt++)
                    mma16816(acc[mt][nt], a_, &w_[nt >> 1][(nt & 1) * 2]);
            }
        }
        __syncthreads();

        // refill this stage with chunk c+NSTAGE
        const int cn = c + NSTAGE;
        if (cn < NCHUNK) {
            #pragma unroll
            for (int i = 0; i < 2; i++) {
                cp16(soff + OFF_AHI + dst_off[i], ahi_p[i] + cn * BK, abytes[i]);
                cp16(soff + OFF_ALO + dst_off[i], alo_p[i] + cn * BK, abytes[i]);
                cp16(soff + OFF_W   + dst_off[i], w_p[i]   + cn * BK, 16u);
            }
        }
        cp_commit();                // unconditional: keeps group counting uniform
        stage = (stage + 1 == NSTAGE) ? 0 : stage + 1;
    }

    // ---- epilogue: scatter accumulators to out
    const int rbase = warp_m * 64 + (lane >> 2);
    const int cbase = col0 + warp_n * 32 + (lane & 3) * 2;
    #pragma unroll
    for (int mt = 0; mt < 4; mt++) {
        int r0 = srows[rbase + mt * 16];
        int r1 = srows[rbase + mt * 16 + 8];
        #pragma unroll
        for (int nt = 0; nt < 4; nt++) {
            int col = cbase + nt * 8;
            if (r0 >= 0)
                *reinterpret_cast<float2*>(out + (size_t)r0 * OUT_FEAT + col) =
                    make_float2(acc[mt][nt][0], acc[mt][nt][1]);
            if (r1 >= 0)
                *reinterpret_cast<float2*>(out + (size_t)r1 * OUT_FEAT + col) =
                    make_float2(acc[mt][nt][2], acc[mt][nt][3]);
        }
    }
}

extern "C" void kernel_launch(void* const* d_in, const int* in_sizes, int n_in,
                              void* d_out, int out_size) {
    const float* inp    = (const float*)d_in[0];   // [8192, 1024] f32
    const int*   gate   = (const int*)d_in[1];     // [8192] i32
    const float* weight = (const float*)d_in[2];   // [16, 1024, 1024] f32
    float* out = (float*)d_out;                    // [8192, 1024] f32

    cudaFuncSetAttribute(moe_mma_kernel, cudaFuncAttributeMaxDynamicSharedMemorySize,
                         SMEM_TOTAL);

    reset_counts_kernel<<<1, 32>>>();
    scatter_kernel<<<(BATCH + 255) / 256, 256>>>(gate);
    convert_w_kernel<<<NUM_EXPERT * OUT_FEAT * IN_FEAT / 4 / 256, 256>>>(weight);
    convert_a_kernel<<<BATCH * IN_FEAT / 4 / 256, 256>>>(inp);

    dim3 grid(OUT_FEAT / BN, BATCH / BM, NUM_EXPERT);
    moe_mma_kernel<<<grid, THREADS, SMEM_TOTAL>>>(out);
}

// round 7
// speedup vs baseline: 4.4159x; 1.4282x over previous
#include <cuda_runtime.h>
#include <cuda_fp16.h>
#include <cstdint>

#define NUM_EXPERT 16
#define IN_FEAT 1024
#define OUT_FEAT 1024
#define BATCH 8192

#define BM 128
#define BN 128
#define BK 32
#define NCHUNK (IN_FEAT / BK)    // 32
#define THREADS 256
#define SPAD 40                  // fp16 elements per smem row (32 data + 8 pad)
#define TSZ (128 * SPAD * 2)     // one tile: 10240 B
#define NSTAGE 4
#define OFF_A 0
#define OFF_W TSZ
#define STAGE_SZ (2 * TSZ)       // 20480
#define SMEM_TILES 512
#define SMEM_TOTAL (SMEM_TILES + NSTAGE * STAGE_SZ)   // 82432

__device__ int g_counts[NUM_EXPERT];
__device__ int g_rows[NUM_EXPERT * BATCH];
// Precomputed fp16 operands (static scratch; no allocs).
__device__ __align__(16) unsigned short g_whi[NUM_EXPERT * OUT_FEAT * IN_FEAT]; // 33.5 MB
__device__ __align__(16) unsigned short g_ahi[BATCH * IN_FEAT];                 // 16.8 MB

// ---------------- helpers ----------------
__device__ __forceinline__ uint32_t smem_u32(const void* p) {
    uint32_t a;
    asm("{ .reg .u64 t; cvta.to.shared.u64 t, %1; cvt.u32.u64 %0, t; }" : "=r"(a) : "l"(p));
    return a;
}
__device__ __forceinline__ uint32_t pack_h2(float x, float y) {
    uint32_t r;
    asm("cvt.rn.f16x2.f32 %0, %1, %2;" : "=r"(r) : "f"(y), "f"(x));  // y->hi, x->lo
    return r;
}
__device__ __forceinline__ void cp16(uint32_t dst, const void* src, uint32_t bytes) {
    asm volatile("cp.async.cg.shared.global [%0], [%1], 16, %2;"
                 :: "r"(dst), "l"(src), "r"(bytes) : "memory");
}
__device__ __forceinline__ void cp_commit() {
    asm volatile("cp.async.commit_group;" ::: "memory");
}
template <int N>
__device__ __forceinline__ void cp_wait() {
    asm volatile("cp.async.wait_group %0;" :: "n"(N) : "memory");
}
__device__ __forceinline__ void ldsm4(uint32_t* r, uint32_t addr) {
    asm volatile("ldmatrix.sync.aligned.m8n8.x4.shared.b16 {%0,%1,%2,%3}, [%4];"
                 : "=r"(r[0]), "=r"(r[1]), "=r"(r[2]), "=r"(r[3]) : "r"(addr));
}
__device__ __forceinline__ void mma16816(float* d, const uint32_t* a, const uint32_t* b) {
    asm volatile(
        "mma.sync.aligned.m16n8k16.row.col.f32.f16.f16.f32 "
        "{%0,%1,%2,%3}, {%4,%5,%6,%7}, {%8,%9}, {%0,%1,%2,%3};"
        : "+f"(d[0]), "+f"(d[1]), "+f"(d[2]), "+f"(d[3])
        : "r"(a[0]), "r"(a[1]), "r"(a[2]), "r"(a[3]), "r"(b[0]), "r"(b[1]));
}

// ---------------- fused prepasses ----------------
// convert_w also resets the expert counters (block 0).
__global__ __launch_bounds__(256)
void convert_w_kernel(const float* __restrict__ w) {
    if (blockIdx.x == 0 && threadIdx.x < NUM_EXPERT) g_counts[threadIdx.x] = 0;
    int i = blockIdx.x * blockDim.x + threadIdx.x;   // one float4
    float4 v = reinterpret_cast<const float4*>(w)[i];
    uint2 h;
    h.x = pack_h2(v.x, v.y);
    h.y = pack_h2(v.z, v.w);
    reinterpret_cast<uint2*>(g_whi)[i] = h;
}
// convert_a also scatters gate routing (first BATCH threads).
__global__ __launch_bounds__(256)
void convert_a_kernel(const float* __restrict__ a, const int* __restrict__ gate) {
    int i = blockIdx.x * blockDim.x + threadIdx.x;   // one float4
    if (i < BATCH) {
        int e = gate[i];
        int pos = atomicAdd(&g_counts[e], 1);
        g_rows[e * BATCH + pos] = i;
    }
    float4 v = reinterpret_cast<const float4*>(a)[i];
    uint2 h;
    h.x = pack_h2(v.x, v.y);
    h.y = pack_h2(v.z, v.w);
    reinterpret_cast<uint2*>(g_ahi)[i] = h;
}

// ---------------- grouped GEMM (single-pass fp16, cp.async 4-stage) ----------------
__global__ __launch_bounds__(THREADS, 2)
void moe_mma_kernel(float* __restrict__ out) {
    const int e = blockIdx.z;
    const int cnt = g_counts[e];
    const int row0 = blockIdx.y * BM;
    if (row0 >= cnt) return;
    const int col0 = blockIdx.x * BN;

    extern __shared__ char smem[];
    int* srows = (int*)smem;

    const int tid = threadIdx.x;
    const int wid = tid >> 5;
    const int lane = tid & 31;
    const int warp_m = wid >> 2;      // 0..1 -> 64-row half
    const int warp_n = wid & 3;       // 0..3 -> 32-col quarter

    if (tid < BM) {
        int r = row0 + tid;
        srows[tid] = (r < cnt) ? g_rows[e * BATCH + r] : -1;
    }
    __syncthreads();

    const uint32_t sb = smem_u32(smem);
    const uint32_t TILES = sb + SMEM_TILES;

    // ---- per-thread cp.async assignments: 2 x (A, W) 16B chunks per K-chunk
    const unsigned short* a_p[2];
    const unsigned short* w_p[2];
    uint32_t dst_off[2], abytes[2];
    #pragma unroll
    for (int i = 0; i < 2; i++) {
        int idx = tid + i * THREADS;   // 0..511
        int m  = idx >> 2;             // row 0..127
        int kq = idx & 3;              // 16B quarter of the 64B row
        dst_off[i] = (uint32_t)(m * (SPAD * 2) + kq * 16);
        int r = srows[m];
        abytes[i] = (r >= 0) ? 16u : 0u;
        a_p[i] = g_ahi + (size_t)(r < 0 ? 0 : r) * IN_FEAT + kq * 8;
        w_p[i] = g_whi + ((size_t)e * OUT_FEAT + col0 + m) * IN_FEAT + kq * 8;
    }

    // ---- ldmatrix per-lane offsets (bytes within a tile)
    const int arow  = lane & 15;
    const int akoff = (lane >> 4) << 3;
    const uint32_t a_off = (uint32_t)((warp_m * 64 + arow) * SPAD + akoff) * 2;
    const int brow  = ((lane >> 4) << 3) + (lane & 7);
    const int bkoff = ((lane >> 3) & 1) << 3;
    const uint32_t b_off = (uint32_t)((warp_n * 32 + brow) * SPAD + bkoff) * 2;

    float acc[4][4][4];
    #pragma unroll
    for (int mt = 0; mt < 4; mt++)
        #pragma unroll
        for (int nt = 0; nt < 4; nt++)
            #pragma unroll
            for (int q = 0; q < 4; q++) acc[mt][nt][q] = 0.0f;

    // ---- prologue: prefetch stages 0..NSTAGE-1
    #pragma unroll
    for (int s = 0; s < NSTAGE; s++) {
        uint32_t base = TILES + s * STAGE_SZ;
        #pragma unroll
        for (int i = 0; i < 2; i++) {
            cp16(base + OFF_A + dst_off[i], a_p[i] + s * BK, abytes[i]);
            cp16(base + OFF_W + dst_off[i], w_p[i] + s * BK, 16u);
        }
        cp_commit();
    }

    int stage = 0;
    #pragma unroll 1
    for (int c = 0; c < NCHUNK; c++) {
        cp_wait<NSTAGE - 1>();      // chunk c landed
        __syncthreads();

        const uint32_t soff = TILES + (uint32_t)stage * STAGE_SZ;
        #pragma unroll
        for (int ks = 0; ks < 2; ks++) {
            uint32_t w_[2][4];
            ldsm4(w_[0], soff + OFF_W + b_off + ks * 32);
            ldsm4(w_[1], soff + OFF_W + b_off + ks * 32 + 16 * SPAD * 2);
            #pragma unroll
            for (int mt = 0; mt < 4; mt++) {
                uint32_t a_[4];
                ldsm4(a_, soff + OFF_A + a_off + ks * 32 + mt * (16 * SPAD * 2));
                #pragma unroll
                for (int nt = 0; nt < 4; nt++)
                    mma16816(acc[mt][nt], a_, &w_[nt >> 1][(nt & 1) * 2]);
            }
        }
        __syncthreads();

        // refill this stage with chunk c+NSTAGE
        const int cn = c + NSTAGE;
        if (cn < NCHUNK) {
            #pragma unroll
            for (int i = 0; i < 2; i++) {
                cp16(soff + OFF_A + dst_off[i], a_p[i] + cn * BK, abytes[i]);
                cp16(soff + OFF_W + dst_off[i], w_p[i] + cn * BK, 16u);
            }
        }
        cp_commit();                // unconditional: keeps group counting uniform
        stage = (stage + 1 == NSTAGE) ? 0 : stage + 1;
    }

    // ---- epilogue: scatter accumulators to out
    const int rbase = warp_m * 64 + (lane >> 2);
    const int cbase = col0 + warp_n * 32 + (lane & 3) * 2;
    #pragma unroll
    for (int mt = 0; mt < 4; mt++) {
        int r0 = srows[rbase + mt * 16];
        int r1 = srows[rbase + mt * 16 + 8];
        #pragma unroll
        for (int nt = 0; nt < 4; nt++) {
            int col = cbase + nt * 8;
            if (r0 >= 0)
                *reinterpret_cast<float2*>(out + (size_t)r0 * OUT_FEAT + col) =
                    make_float2(acc[mt][nt][0], acc[mt][nt][1]);
            if (r1 >= 0)
                *reinterpret_cast<float2*>(out + (size_t)r1 * OUT_FEAT + col) =
                    make_float2(acc[mt][nt][2], acc[mt][nt][3]);
        }
    }
}

extern "C" void kernel_launch(void* const* d_in, const int* in_sizes, int n_in,
                              void* d_out, int out_size) {
    const float* inp    = (const float*)d_in[0];   // [8192, 1024] f32
    const int*   gate   = (const int*)d_in[1];     // [8192] i32
    const float* weight = (const float*)d_in[2];   // [16, 1024, 1024] f32
    float* out = (float*)d_out;                    // [8192, 1024] f32

    cudaFuncSetAttribute(moe_mma_kernel, cudaFuncAttributeMaxDynamicSharedMemorySize,
                         SMEM_TOTAL);

    convert_w_kernel<<<NUM_EXPERT * OUT_FEAT * IN_FEAT / 4 / 256, 256>>>(weight);
    convert_a_kernel<<<BATCH * IN_FEAT / 4 / 256, 256>>>(inp, gate);

    dim3 grid(OUT_FEAT / BN, BATCH / BM, NUM_EXPERT);
    moe_mma_kernel<<<grid, THREADS, SMEM_TOTAL>>>(out);
}